// round 6
// baseline (speedup 1.0000x reference)
#include <cuda_runtime.h>

// Problem constants
#define TPB    256
#define NSAMP  32000      // B*length = 32*1000
#define LEN    1000
#define TROW   1002
#define DDIM   16
#define EDIM   32
#define HDIM   64

typedef unsigned long long u64;

// Packed fp32x2 FMA (Blackwell sm_10x): d = a*b + c on two packed fp32 lanes.
__device__ __forceinline__ u64 ffma2(u64 a, u64 b, u64 c) {
    u64 d;
    asm("fma.rn.f32x2 %0, %1, %2, %3;" : "=l"(d) : "l"(a), "l"(b), "l"(c));
    return d;
}
__device__ __forceinline__ float hsum2(u64 v) {
    float lo, hi;
    asm("mov.b64 {%0, %1}, %2;" : "=f"(lo), "=f"(hi) : "l"(v));
    return lo + hi;
}
__device__ __forceinline__ u64 pack2(float lo, float hi) {
    u64 v;
    asm("mov.b64 %0, {%1, %2};" : "=l"(v) : "f"(lo), "f"(hi));
    return v;
}

// Scratch for per-(d, n) log|dJ| — deterministic reduction in a second kernel.
__device__ float g_dj[DDIM * NSAMP];

// Shared memory layout (float offsets):
//   stage  : u64[32 * TPB]          -> floats [0, 16384)        (65536 B)
//   sW1    : 64x64                  -> [16384, 20480)
//   sW2    : 64x64                  -> [20480, 24576)
//   sW0e   : 64x32                  -> [24576, 26624)
//   sW0x   : 64                     -> [26624, 26688)
//   sWo    : 64                     -> [26688, 26752)
//   sB0/sB1/sB2 : 3x64              -> [26752, 26944)
#define SMEM_BYTES (26944 * 4)   // 107776 B -> 2 blocks/SM (215552 <= 228K)

// ---- a-path hidden layer: z = W@a + b, leaky gate, record gate mask ----
__device__ __forceinline__ void a_pass64(const float* __restrict__ sW,
                                         const float* __restrict__ sB,
                                         u64* __restrict__ stage,
                                         u64* __restrict__ apk,
                                         u64& mask, int tid)
{
    u64 m = 0;
#pragma unroll 1
    for (int i = 0; i < HDIM; i += 4) {
        u64 acc0 = 0, acc1 = 0, acc2 = 0, acc3 = 0;
        const ulonglong2* r0 = (const ulonglong2*)(sW + (i + 0) * HDIM);
        const ulonglong2* r1 = (const ulonglong2*)(sW + (i + 1) * HDIM);
        const ulonglong2* r2 = (const ulonglong2*)(sW + (i + 2) * HDIM);
        const ulonglong2* r3 = (const ulonglong2*)(sW + (i + 3) * HDIM);
#pragma unroll
        for (int k = 0; k < 16; ++k) {
            ulonglong2 w0 = r0[k], w1 = r1[k], w2 = r2[k], w3 = r3[k];
            u64 a0 = apk[2 * k], a1 = apk[2 * k + 1];
            acc0 = ffma2(w0.x, a0, acc0); acc0 = ffma2(w0.y, a1, acc0);
            acc1 = ffma2(w1.x, a0, acc1); acc1 = ffma2(w1.y, a1, acc1);
            acc2 = ffma2(w2.x, a0, acc2); acc2 = ffma2(w2.y, a1, acc2);
            acc3 = ffma2(w3.x, a0, acc3); acc3 = ffma2(w3.y, a1, acc3);
        }
        float z0 = hsum2(acc0) + sB[i + 0];
        float z1 = hsum2(acc1) + sB[i + 1];
        float z2 = hsum2(acc2) + sB[i + 2];
        float z3 = hsum2(acc3) + sB[i + 3];
        float a0v = (z0 >= 0.f) ? z0 : 0.2f * z0;
        float a1v = (z1 >= 0.f) ? z1 : 0.2f * z1;
        float a2v = (z2 >= 0.f) ? z2 : 0.2f * z2;
        float a3v = (z3 >= 0.f) ? z3 : 0.2f * z3;
        m |= (u64)(z0 < 0.f) << (i + 0);
        m |= (u64)(z1 < 0.f) << (i + 1);
        m |= (u64)(z2 < 0.f) << (i + 2);
        m |= (u64)(z3 < 0.f) << (i + 3);
        stage[((i >> 1) + 0) * TPB + tid] = pack2(a0v, a1v);
        stage[((i >> 1) + 1) * TPB + tid] = pack2(a2v, a3v);
    }
    mask = m;
#pragma unroll
    for (int p = 0; p < 32; ++p) apk[p] = stage[p * TPB + tid];
}

// ---- t-path hidden layer: t_new = gate(mask) * (W @ t_old) ----
__device__ __forceinline__ void t_pass64(const float* __restrict__ sW,
                                         u64 mask,
                                         u64* __restrict__ stage,
                                         u64* __restrict__ tpk, int tid)
{
#pragma unroll 1
    for (int i = 0; i < HDIM; i += 4) {
        u64 acc0 = 0, acc1 = 0, acc2 = 0, acc3 = 0;
        const ulonglong2* r0 = (const ulonglong2*)(sW + (i + 0) * HDIM);
        const ulonglong2* r1 = (const ulonglong2*)(sW + (i + 1) * HDIM);
        const ulonglong2* r2 = (const ulonglong2*)(sW + (i + 2) * HDIM);
        const ulonglong2* r3 = (const ulonglong2*)(sW + (i + 3) * HDIM);
#pragma unroll
        for (int k = 0; k < 16; ++k) {
            ulonglong2 w0 = r0[k], w1 = r1[k], w2 = r2[k], w3 = r3[k];
            u64 t0 = tpk[2 * k], t1 = tpk[2 * k + 1];
            acc0 = ffma2(w0.x, t0, acc0); acc0 = ffma2(w0.y, t1, acc0);
            acc1 = ffma2(w1.x, t0, acc1); acc1 = ffma2(w1.y, t1, acc1);
            acc2 = ffma2(w2.x, t0, acc2); acc2 = ffma2(w2.y, t1, acc2);
            acc3 = ffma2(w3.x, t0, acc3); acc3 = ffma2(w3.y, t1, acc3);
        }
        float v0 = hsum2(acc0);
        float v1 = hsum2(acc1);
        float v2 = hsum2(acc2);
        float v3 = hsum2(acc3);
        v0 = ((mask >> (i + 0)) & 1ull) ? 0.2f * v0 : v0;
        v1 = ((mask >> (i + 1)) & 1ull) ? 0.2f * v1 : v1;
        v2 = ((mask >> (i + 2)) & 1ull) ? 0.2f * v2 : v2;
        v3 = ((mask >> (i + 3)) & 1ull) ? 0.2f * v3 : v3;
        stage[((i >> 1) + 0) * TPB + tid] = pack2(v0, v1);
        stage[((i >> 1) + 1) * TPB + tid] = pack2(v2, v3);
    }
#pragma unroll
    for (int p = 0; p < 32; ++p) tpk[p] = stage[p * TPB + tid];
}

extern "C" __global__ void __launch_bounds__(TPB, 2)
mlp_fwd_kernel(const float* __restrict__ x,  const float* __restrict__ emb,
               const float* __restrict__ W0, const float* __restrict__ b0,
               const float* __restrict__ W1, const float* __restrict__ b1,
               const float* __restrict__ W2, const float* __restrict__ b2,
               const float* __restrict__ Wo, const float* __restrict__ bo,
               float* __restrict__ out)
{
    extern __shared__ float smem[];
    const int tid = threadIdx.x;
    const int d   = blockIdx.y;

    u64*   stage = (u64*)smem;
    float* sW1   = smem + 16384;
    float* sW2   = sW1 + 4096;
    float* sW0e  = sW2 + 4096;
    float* sW0x  = sW0e + 2048;
    float* sWo   = sW0x + 64;
    float* sB0   = sWo + 64;
    float* sB1   = sB0 + 64;
    float* sB2   = sB1 + 64;

    // ---- cooperative weight staging ----
    {
        const float4* g1 = (const float4*)(W1 + d * 4096);
        const float4* g2 = (const float4*)(W2 + d * 4096);
        float4* s1 = (float4*)sW1;
        float4* s2 = (float4*)sW2;
#pragma unroll
        for (int k = 0; k < 4; ++k) {
            s1[tid + k * TPB] = g1[tid + k * TPB];
            s2[tid + k * TPB] = g2[tid + k * TPB];
        }
        const float* g0 = W0 + d * HDIM * (EDIM + 1);
        for (int idx = tid; idx < HDIM * EDIM; idx += TPB) {
            int h = idx >> 5, e = idx & 31;
            sW0e[idx] = g0[h * 33 + e];
        }
        if (tid < HDIM) {
            sW0x[tid] = g0[tid * 33 + 32];
            sWo[tid]  = Wo[d * HDIM + tid];
            sB0[tid]  = b0[d * HDIM + tid];
            sB1[tid]  = b1[d * HDIM + tid];
            sB2[tid]  = b2[d * HDIM + tid];
        }
    }
    __syncthreads();

    const int n   = blockIdx.x * TPB + tid;     // grid.x*TPB == NSAMP exactly
    const int b   = n / LEN;
    const int l   = n - b * LEN;
    const int row = b * TROW + 2 + l;           // LAGS = 2
    const float xt = x[row * DDIM + d];

    // Pack the 32-wide embedding into 16 f32x2 regs.
    u64 epk[16];
    {
        const float4* er = (const float4*)(emb + (size_t)row * EDIM);
#pragma unroll
        for (int k = 0; k < 8; ++k) {
            float4 v = er[k];
            epk[2 * k]     = pack2(v.x, v.y);
            epk[2 * k + 1] = pack2(v.z, v.w);
        }
    }

    u64 apk[32];
    u64 mask0, mask1, mask2;

    // ================= a-phase =================
    // layer 0: z0 = W0e @ emb + W0x * x + b0
    {
        u64 m = 0;
#pragma unroll 1
        for (int i = 0; i < HDIM; i += 4) {
            u64 acc0 = 0, acc1 = 0, acc2 = 0, acc3 = 0;
            const ulonglong2* r0 = (const ulonglong2*)(sW0e + (i + 0) * EDIM);
            const ulonglong2* r1 = (const ulonglong2*)(sW0e + (i + 1) * EDIM);
            const ulonglong2* r2 = (const ulonglong2*)(sW0e + (i + 2) * EDIM);
            const ulonglong2* r3 = (const ulonglong2*)(sW0e + (i + 3) * EDIM);
#pragma unroll
            for (int k = 0; k < 8; ++k) {
                ulonglong2 w0 = r0[k], w1 = r1[k], w2 = r2[k], w3 = r3[k];
                u64 e0 = epk[2 * k], e1 = epk[2 * k + 1];
                acc0 = ffma2(w0.x, e0, acc0); acc0 = ffma2(w0.y, e1, acc0);
                acc1 = ffma2(w1.x, e0, acc1); acc1 = ffma2(w1.y, e1, acc1);
                acc2 = ffma2(w2.x, e0, acc2); acc2 = ffma2(w2.y, e1, acc2);
                acc3 = ffma2(w3.x, e0, acc3); acc3 = ffma2(w3.y, e1, acc3);
            }
            float z0 = hsum2(acc0) + sW0x[i + 0] * xt + sB0[i + 0];
            float z1 = hsum2(acc1) + sW0x[i + 1] * xt + sB0[i + 1];
            float z2 = hsum2(acc2) + sW0x[i + 2] * xt + sB0[i + 2];
            float z3 = hsum2(acc3) + sW0x[i + 3] * xt + sB0[i + 3];
            float a0v = (z0 >= 0.f) ? z0 : 0.2f * z0;
            float a1v = (z1 >= 0.f) ? z1 : 0.2f * z1;
            float a2v = (z2 >= 0.f) ? z2 : 0.2f * z2;
            float a3v = (z3 >= 0.f) ? z3 : 0.2f * z3;
            m |= (u64)(z0 < 0.f) << (i + 0);
            m |= (u64)(z1 < 0.f) << (i + 1);
            m |= (u64)(z2 < 0.f) << (i + 2);
            m |= (u64)(z3 < 0.f) << (i + 3);
            stage[((i >> 1) + 0) * TPB + tid] = pack2(a0v, a1v);
            stage[((i >> 1) + 1) * TPB + tid] = pack2(a2v, a3v);
        }
        mask0 = m;
#pragma unroll
        for (int p = 0; p < 32; ++p) apk[p] = stage[p * TPB + tid];
    }

    a_pass64(sW1, sB1, stage, apk, mask1, tid);
    a_pass64(sW2, sB2, stage, apk, mask2, tid);

    // residual head
    {
        u64 ra = 0;
        const ulonglong2* wo = (const ulonglong2*)sWo;
#pragma unroll
        for (int k = 0; k < 16; ++k) {
            ulonglong2 w = wo[k];
            ra = ffma2(w.x, apk[2 * k],     ra);
            ra = ffma2(w.y, apk[2 * k + 1], ra);
        }
        out[n * DDIM + d] = hsum2(ra) + bo[d];
    }

    // ================= t-phase =================
    u64 tpk[32];
    {
        const ulonglong2* wx = (const ulonglong2*)sW0x;
#pragma unroll
        for (int q = 0; q < 16; ++q) {
            ulonglong2 w = wx[q];                 // 4 floats of W0x
            float w0 = hsum2(pack2(0.f, 0.f));    // placeholder avoided below
            // unpack 4 floats from the two u64s
            float f0, f1, f2, f3;
            asm("mov.b64 {%0, %1}, %2;" : "=f"(f0), "=f"(f1) : "l"(w.x));
            asm("mov.b64 {%0, %1}, %2;" : "=f"(f2), "=f"(f3) : "l"(w.y));
            int i = q * 4;
            f0 = ((mask0 >> (i + 0)) & 1ull) ? 0.2f * f0 : f0;
            f1 = ((mask0 >> (i + 1)) & 1ull) ? 0.2f * f1 : f1;
            f2 = ((mask0 >> (i + 2)) & 1ull) ? 0.2f * f2 : f2;
            f3 = ((mask0 >> (i + 3)) & 1ull) ? 0.2f * f3 : f3;
            tpk[2 * q]     = pack2(f0, f1);
            tpk[2 * q + 1] = pack2(f2, f3);
            (void)w0;
        }
    }

    t_pass64(sW1, mask1, stage, tpk, tid);
    t_pass64(sW2, mask2, stage, tpk, tid);

    // Jacobian head
    {
        u64 rt = 0;
        const ulonglong2* wo = (const ulonglong2*)sWo;
#pragma unroll
        for (int k = 0; k < 16; ++k) {
            ulonglong2 w = wo[k];
            rt = ffma2(w.x, tpk[2 * k],     rt);
            rt = ffma2(w.y, tpk[2 * k + 1], rt);
        }
        g_dj[d * NSAMP + n] = logf(fabsf(hsum2(rt)));
    }
}

extern "C" __global__ void __launch_bounds__(256)
reduce_logdet_kernel(float* __restrict__ out)
{
    int n = blockIdx.x * 256 + threadIdx.x;
    if (n < NSAMP) {
        float s = 0.f;
#pragma unroll
        for (int d = 0; d < DDIM; ++d) s += g_dj[d * NSAMP + n];
        out[NSAMP * DDIM + n] = s;   // logdet region after residuals
    }
}

extern "C" void kernel_launch(void* const* d_in, const int* in_sizes, int n_in,
                              void* d_out, int out_size)
{
    const float* x   = (const float*)d_in[0];
    const float* emb = (const float*)d_in[1];
    const float* W0  = (const float*)d_in[2];
    const float* b0  = (const float*)d_in[3];
    const float* W1  = (const float*)d_in[4];
    const float* b1  = (const float*)d_in[5];
    const float* W2  = (const float*)d_in[6];
    const float* b2  = (const float*)d_in[7];
    const float* Wo  = (const float*)d_in[8];
    const float* bo  = (const float*)d_in[9];
    float* out = (float*)d_out;

    // Idempotent opt-in for >48KB dynamic smem (capture-safe, not a stream op).
    cudaFuncSetAttribute(mlp_fwd_kernel,
                         cudaFuncAttributeMaxDynamicSharedMemorySize, SMEM_BYTES);

    dim3 grid(NSAMP / TPB, DDIM);   // (125, 16)
    mlp_fwd_kernel<<<grid, TPB, SMEM_BYTES>>>(x, emb, W0, b0, W1, b1, W2, b2,
                                              Wo, bo, out);
    reduce_logdet_kernel<<<(NSAMP + 255) / 256, 256>>>(out);
}

// round 8
// speedup vs baseline: 1.0493x; 1.0493x over previous
#include <cuda_runtime.h>

// Problem constants
#define TPB    128
#define NSAMP  32000      // B*length = 32*1000
#define LEN    1000
#define TROW   1002
#define DDIM   16
#define EDIM   32
#define HDIM   64

typedef unsigned long long u64;

// Packed fp32x2 FMA (Blackwell sm_10x): d = a*b + c on two packed fp32 lanes.
__device__ __forceinline__ u64 ffma2(u64 a, u64 b, u64 c) {
    u64 d;
    asm("fma.rn.f32x2 %0, %1, %2, %3;" : "=l"(d) : "l"(a), "l"(b), "l"(c));
    return d;
}
__device__ __forceinline__ float hsum2(u64 v) {
    float lo, hi;
    asm("mov.b64 {%0, %1}, %2;" : "=f"(lo), "=f"(hi) : "l"(v));
    return lo + hi;
}
__device__ __forceinline__ u64 pack2(float lo, float hi) {
    u64 v;
    asm("mov.b64 %0, {%1, %2};" : "=l"(v) : "f"(lo), "f"(hi));
    return v;
}
__device__ __forceinline__ void unpack2(u64 v, float& lo, float& hi) {
    asm("mov.b64 {%0, %1}, %2;" : "=f"(lo), "=f"(hi) : "l"(v));
}

// Scratch for per-(d, n) log|dJ| — deterministic reduction in a second kernel.
__device__ float g_dj[DDIM * NSAMP];

// Shared memory layout (float offsets), static (<48KB):
#define OFF_W0E  0        // 64 x 32
#define OFF_W1T  2048     // 64 cols x 72 stride (padded transpose of W1)
#define OFF_W2   6656     // 64 x 64 row-major
#define OFF_W0X  10752    // 64
#define OFF_WO   10816    // 64
#define OFF_B0   10880    // 64
#define OFF_B1   10944    // 64
#define OFF_B2   11008    // 64
#define SMEM_FLOATS 11072 // 44288 bytes -> 3 blocks/SM by smem
#define W1T_STRIDE 72     // 288B per col: 16B-aligned, staging conflicts 4-way

extern "C" __global__ void __launch_bounds__(TPB, 3)
mlp_fwd_kernel(const float* __restrict__ x,  const float* __restrict__ emb,
               const float* __restrict__ W0, const float* __restrict__ b0,
               const float* __restrict__ W1, const float* __restrict__ b1,
               const float* __restrict__ W2, const float* __restrict__ b2,
               const float* __restrict__ Wo, const float* __restrict__ bo,
               float* __restrict__ out)
{
    __shared__ float smem[SMEM_FLOATS];
    const int tid = threadIdx.x;
    const int d   = blockIdx.y;

    float* sW0e = smem + OFF_W0E;
    float* sW1T = smem + OFF_W1T;
    float* sW2  = smem + OFF_W2;
    float* sW0x = smem + OFF_W0X;
    float* sWo  = smem + OFF_WO;
    float* sB0  = smem + OFF_B0;
    float* sB1  = smem + OFF_B1;
    float* sB2  = smem + OFF_B2;

    // ---- cooperative weight staging ----
    {
        const float* g0 = W0 + d * HDIM * (EDIM + 1);   // 64 x 33
#pragma unroll 1
        for (int idx = tid; idx < HDIM * (EDIM + 1); idx += TPB) {
            int h = idx / 33, e = idx - h * 33;
            float v = g0[idx];
            if (e == 32) sW0x[h] = v; else sW0e[h * EDIM + e] = v;
        }
        const float* g1 = W1 + d * 4096;
#pragma unroll 1
        for (int idx = tid; idx < 4096; idx += TPB) {
            int j = idx >> 6, i = idx & 63;
            sW1T[i * W1T_STRIDE + j] = g1[idx];         // transpose: col i contiguous
        }
        const float4* g2 = (const float4*)(W2 + d * 4096);
        float4* s2 = (float4*)sW2;
#pragma unroll
        for (int k = 0; k < 8; ++k) s2[tid + k * TPB] = g2[tid + k * TPB];
        if (tid < HDIM) {
            sWo[tid] = Wo[d * HDIM + tid];
            sB0[tid] = b0[d * HDIM + tid];
            sB1[tid] = b1[d * HDIM + tid];
            sB2[tid] = b2[d * HDIM + tid];
        }
    }
    __syncthreads();

    const int n   = blockIdx.x * TPB + tid;     // grid.x*TPB == NSAMP exactly
    const int b   = n / LEN;
    const int l   = n - b * LEN;
    const int row = b * TROW + 2 + l;           // LAGS = 2
    const float xt = x[row * DDIM + d];

    // Pack the 32-wide embedding into 16 f32x2 regs.
    u64 epk[16];
    {
        const float4* er = (const float4*)(emb + (size_t)row * EDIM);
#pragma unroll
        for (int k = 0; k < 8; ++k) {
            float4 v = er[k];
            epk[2 * k]     = pack2(v.x, v.y);
            epk[2 * k + 1] = pack2(v.z, v.w);
        }
    }

    u64 accA[32];
#pragma unroll
    for (int p = 0; p < 32; ++p) accA[p] = 0;
    u64 mask0 = 0;

    // ===== Phase A: layer0 rows (a-path) fused with column-accumulate into W1 =====
#pragma unroll 1
    for (int i = 0; i < HDIM; i += 2) {
        u64 d0a = 0, d0b = 0, d1a = 0, d1b = 0;
        const ulonglong2* r0 = (const ulonglong2*)(sW0e + i * EDIM);
        const ulonglong2* r1 = r0 + 8;   // next row (32 floats = 8 x 16B)
#pragma unroll
        for (int k = 0; k < 8; ++k) {
            ulonglong2 w0 = r0[k], w1 = r1[k];
            u64 e0 = epk[2 * k], e1 = epk[2 * k + 1];
            d0a = ffma2(w0.x, e0, d0a);
            d1a = ffma2(w1.x, e0, d1a);
            d0b = ffma2(w0.y, e1, d0b);
            d1b = ffma2(w1.y, e1, d1b);
        }
        float z0 = hsum2(d0a) + hsum2(d0b) + sW0x[i + 0] * xt + sB0[i + 0];
        float z1 = hsum2(d1a) + hsum2(d1b) + sW0x[i + 1] * xt + sB0[i + 1];
        float a0 = (z0 >= 0.f) ? z0 : 0.2f * z0;
        float a1 = (z1 >= 0.f) ? z1 : 0.2f * z1;
        mask0 |= (u64)(z0 < 0.f) << i;
        mask0 |= (u64)(z1 < 0.f) << (i + 1);
        u64 av0 = pack2(a0, a0), av1 = pack2(a1, a1);
        const ulonglong2* c0 = (const ulonglong2*)(sW1T + (i + 0) * W1T_STRIDE);
        const ulonglong2* c1 = (const ulonglong2*)(sW1T + (i + 1) * W1T_STRIDE);
#pragma unroll
        for (int k = 0; k < 16; ++k) {
            ulonglong2 w0 = c0[k], w1 = c1[k];
            accA[2 * k]     = ffma2(av0, w0.x, accA[2 * k]);
            accA[2 * k + 1] = ffma2(av0, w0.y, accA[2 * k + 1]);
            accA[2 * k]     = ffma2(av1, w1.x, accA[2 * k]);
            accA[2 * k + 1] = ffma2(av1, w1.y, accA[2 * k + 1]);
        }
    }

    // ===== Phase B: t-path layer0 (from mask) + column-accumulate into W1 =====
    u64 accT[32];
#pragma unroll
    for (int p = 0; p < 32; ++p) accT[p] = 0;
#pragma unroll 1
    for (int i = 0; i < HDIM; i += 2) {
        float w0v = sW0x[i], w1v = sW0x[i + 1];
        float t0 = ((mask0 >> i) & 1ull)       ? 0.2f * w0v : w0v;
        float t1 = ((mask0 >> (i + 1)) & 1ull) ? 0.2f * w1v : w1v;
        u64 tv0 = pack2(t0, t0), tv1 = pack2(t1, t1);
        const ulonglong2* c0 = (const ulonglong2*)(sW1T + (i + 0) * W1T_STRIDE);
        const ulonglong2* c1 = (const ulonglong2*)(sW1T + (i + 1) * W1T_STRIDE);
#pragma unroll
        for (int k = 0; k < 16; ++k) {
            ulonglong2 w0 = c0[k], w1 = c1[k];
            accT[2 * k]     = ffma2(tv0, w0.x, accT[2 * k]);
            accT[2 * k + 1] = ffma2(tv0, w0.y, accT[2 * k + 1]);
            accT[2 * k]     = ffma2(tv1, w1.x, accT[2 * k]);
            accT[2 * k + 1] = ffma2(tv1, w1.y, accT[2 * k + 1]);
        }
    }

    // ===== Gate layer 1 in place: a1 = leaky(accA + b1), t1 = gate * accT =====
    {
        const u64* bb = (const u64*)sB1;
#pragma unroll
        for (int p = 0; p < 32; ++p) {
            float za, zb, b0f, b1f, ta, tb;
            unpack2(accA[p], za, zb);
            unpack2(bb[p],   b0f, b1f);
            unpack2(accT[p], ta, tb);
            za += b0f; zb += b1f;
            float aa = (za >= 0.f) ? za : 0.2f * za;
            float ab = (zb >= 0.f) ? zb : 0.2f * zb;
            float sa = (za >= 0.f) ? ta : 0.2f * ta;
            float sb = (zb >= 0.f) ? tb : 0.2f * tb;
            accA[p] = pack2(aa, ab);
            accT[p] = pack2(sa, sb);
        }
    }

    // ===== Phase C: layer2 rows (both paths) fused with output head =====
    float ra0 = 0.f, ra1 = 0.f, rt0 = 0.f, rt1 = 0.f;
#pragma unroll 1
    for (int j = 0; j < HDIM; j += 2) {
        u64 pa0 = 0, pa1 = 0, pt0 = 0, pt1 = 0;
        const ulonglong2* r0 = (const ulonglong2*)(sW2 + j * HDIM);
        const ulonglong2* r1 = r0 + 16;  // next row (64 floats = 16 x 16B)
#pragma unroll
        for (int k = 0; k < 16; ++k) {
            ulonglong2 w0 = r0[k], w1 = r1[k];
            u64 a0 = accA[2 * k], a1 = accA[2 * k + 1];
            u64 t0 = accT[2 * k], t1 = accT[2 * k + 1];
            pa0 = ffma2(w0.x, a0, pa0);
            pa1 = ffma2(w1.x, a0, pa1);
            pt0 = ffma2(w0.x, t0, pt0);
            pt1 = ffma2(w1.x, t0, pt1);
            pa0 = ffma2(w0.y, a1, pa0);
            pa1 = ffma2(w1.y, a1, pa1);
            pt0 = ffma2(w0.y, t1, pt0);
            pt1 = ffma2(w1.y, t1, pt1);
        }
        float za = hsum2(pa0) + sB2[j + 0];
        float zb = hsum2(pa1) + sB2[j + 1];
        float ta = hsum2(pt0);
        float tb = hsum2(pt1);
        float a2a = (za >= 0.f) ? za : 0.2f * za;
        float a2b = (zb >= 0.f) ? zb : 0.2f * zb;
        float t2a = (za >= 0.f) ? ta : 0.2f * ta;
        float t2b = (zb >= 0.f) ? tb : 0.2f * tb;
        float woa = sWo[j], wob = sWo[j + 1];
        ra0 = fmaf(woa, a2a, ra0);
        ra1 = fmaf(wob, a2b, ra1);
        rt0 = fmaf(woa, t2a, rt0);
        rt1 = fmaf(wob, t2b, rt1);
    }

    out[n * DDIM + d] = ra0 + ra1 + bo[d];
    g_dj[d * NSAMP + n] = logf(fabsf(rt0 + rt1));
}

extern "C" __global__ void __launch_bounds__(256)
reduce_logdet_kernel(float* __restrict__ out)
{
    int n = blockIdx.x * 256 + threadIdx.x;
    if (n < NSAMP) {
        float s = 0.f;
#pragma unroll
        for (int d = 0; d < DDIM; ++d) s += g_dj[d * NSAMP + n];
        out[NSAMP * DDIM + n] = s;   // logdet region after residuals
    }
}

extern "C" void kernel_launch(void* const* d_in, const int* in_sizes, int n_in,
                              void* d_out, int out_size)
{
    const float* x   = (const float*)d_in[0];
    const float* emb = (const float*)d_in[1];
    const float* W0  = (const float*)d_in[2];
    const float* b0  = (const float*)d_in[3];
    const float* W1  = (const float*)d_in[4];
    const float* b1  = (const float*)d_in[5];
    const float* W2  = (const float*)d_in[6];
    const float* b2  = (const float*)d_in[7];
    const float* Wo  = (const float*)d_in[8];
    const float* bo  = (const float*)d_in[9];
    float* out = (float*)d_out;

    dim3 grid(NSAMP / TPB, DDIM);   // (250, 16)
    mlp_fwd_kernel<<<grid, TPB>>>(x, emb, W0, b0, W1, b1, W2, b2, Wo, bo, out);
    reduce_logdet_kernel<<<(NSAMP + 255) / 256, 256>>>(out);
}